// round 1
// baseline (speedup 1.0000x reference)
#include <cuda_runtime.h>
#include <math.h>

#define EPS_BN    1e-5f
#define FT_SMOOTH 1e-5f

#define CH   96
#define HW   128
#define NB   8
#define NPIX (NB*HW*HW)        /* 131072 */

// ---------------- device scratch (alloc-free workaround) ----------------
__device__ float g_q[(size_t)NPIX * CH];
__device__ float g_k[(size_t)NPIX * CH];
__device__ float g_v[(size_t)NPIX * CH];
__device__ float g_att_spat[NPIX];
__device__ float g_part[128 * 96 * 3];
__device__ float g_att_chan[NB * CH];

// ---------------- fractal Tanimoto ----------------
__device__ __forceinline__ float ftanimoto(float tpl, float tpp, float tll) {
    float num = tpl + FT_SMOOTH;
    float s   = tpp + tll;
    float den = 0.f;
#pragma unroll
    for (int d = 0; d < 5; ++d) {
        float a = (float)(1 << d);
        float b = -(2.f * a - 1.f);
        den += 1.f / (a * s + b * tpl + FT_SMOOTH);
    }
    return num * den * 0.2f;
}

__device__ __forceinline__ float sigmoidf_(float x) {
    return 1.f / (1.f + expf(-x));
}

// ---------------- conv 3x3 (96->96) + BN + sigmoid ----------------
// Block: 64 output pixels (one row segment) x 96 couts. 192 threads.
// Thread: 8 px x 4 couts = 32 accumulators.
// smem: input row transposed [96 cin][72 x] (cols 0..65 = gx x0-1..x0+64),
//       weight chunk [3 dx][16 cin][96 cout].
__global__ __launch_bounds__(192)
void conv_bn_sig_kernel(const float* __restrict__ x, const float* __restrict__ w,
                        const float* __restrict__ gamma, const float* __restrict__ beta,
                        const float* __restrict__ mean,  const float* __restrict__ var,
                        float* __restrict__ out)
{
    __shared__ __align__(16) float s_in[96 * 72];      // 27648 B
    __shared__ __align__(16) float s_w[3 * 16 * 96];   // 18432 B

    const int tid = threadIdx.x;
    const int x0  = blockIdx.x * 64;
    const int y   = blockIdx.y;
    const int b   = blockIdx.z;
    const int c0  = (tid % 24) * 4;   // cout base
    const int p0  = (tid / 24) * 8;   // pixel base within tile

    float4 acc[8];
#pragma unroll
    for (int i = 0; i < 8; ++i) acc[i] = make_float4(0.f, 0.f, 0.f, 0.f);

    for (int dy = 0; dy < 3; ++dy) {
        __syncthreads();   // previous chunk compute done before s_in overwrite
        const int gy = y + dy - 1;
        if (gy >= 0 && gy < HW) {
            const float* rowp = x + (size_t)((b * HW + gy) * HW) * CH;
            for (int it = tid; it < 66 * 24; it += 192) {
                int c4  = it % 24;
                int col = it / 24;
                int gx  = x0 + col - 1;
                float4 val = make_float4(0.f, 0.f, 0.f, 0.f);
                if (gx >= 0 && gx < HW)
                    val = *(const float4*)(rowp + gx * CH + c4 * 4);
                int sb = (c4 * 4) * 72 + col;
                s_in[sb]       = val.x;
                s_in[sb + 72]  = val.y;
                s_in[sb + 144] = val.z;
                s_in[sb + 216] = val.w;
            }
        } else {
            for (int it = tid; it < 66 * 24; it += 192) {
                int c4  = it % 24;
                int col = it / 24;
                int sb  = (c4 * 4) * 72 + col;
                s_in[sb] = 0.f; s_in[sb + 72] = 0.f;
                s_in[sb + 144] = 0.f; s_in[sb + 216] = 0.f;
            }
        }
        const float* wslab = w + dy * (3 * CH * CH);   // [dx][cin][cout], contiguous

        for (int cc = 0; cc < 6; ++cc) {
            __syncthreads();  // s_in ready (cc==0) / previous chunk compute done
            // stage weights: [3][16][96] floats = 1152 float4
            for (int it = tid; it < 1152; it += 192) {
                int dx  = it / 384;
                int rem = it % 384;
                int ci  = rem / 24;
                int c4  = rem % 24;
                *(float4*)(s_w + (dx * 16 + ci) * 96 + c4 * 4) =
                    *(const float4*)(wslab + ((dx * 96) + cc * 16 + ci) * 96 + c4 * 4);
            }
            __syncthreads();

            const float* sin_base = s_in + (cc * 16) * 72 + p0;
#pragma unroll 4
            for (int ci = 0; ci < 16; ++ci) {
                const float* ip = sin_base + ci * 72;
                float4 a0 = *(const float4*)(ip);
                float4 a1 = *(const float4*)(ip + 4);
                float in[10];
                in[0] = a0.x; in[1] = a0.y; in[2] = a0.z; in[3] = a0.w;
                in[4] = a1.x; in[5] = a1.y; in[6] = a1.z; in[7] = a1.w;
                in[8] = ip[8]; in[9] = ip[9];
                float4 w0 = *(const float4*)(s_w + (0 * 16 + ci) * 96 + c0);
                float4 w1 = *(const float4*)(s_w + (1 * 16 + ci) * 96 + c0);
                float4 w2 = *(const float4*)(s_w + (2 * 16 + ci) * 96 + c0);
#pragma unroll
                for (int px = 0; px < 8; ++px) {
                    acc[px].x += in[px] * w0.x + in[px + 1] * w1.x + in[px + 2] * w2.x;
                    acc[px].y += in[px] * w0.y + in[px + 1] * w1.y + in[px + 2] * w2.y;
                    acc[px].z += in[px] * w0.z + in[px + 1] * w1.z + in[px + 2] * w2.z;
                    acc[px].w += in[px] * w0.w + in[px + 1] * w1.w + in[px + 2] * w2.w;
                }
            }
        }
    }

    // epilogue: BN + sigmoid, vectorized store
    float4 gm = *(const float4*)(gamma + c0);
    float4 bt = *(const float4*)(beta  + c0);
    float4 mu = *(const float4*)(mean  + c0);
    float4 vr = *(const float4*)(var   + c0);
    float4 sc, sh;
    sc.x = gm.x * rsqrtf(vr.x + EPS_BN); sh.x = bt.x - mu.x * sc.x;
    sc.y = gm.y * rsqrtf(vr.y + EPS_BN); sh.y = bt.y - mu.y * sc.y;
    sc.z = gm.z * rsqrtf(vr.z + EPS_BN); sh.z = bt.z - mu.z * sc.z;
    sc.w = gm.w * rsqrtf(vr.w + EPS_BN); sh.w = bt.w - mu.w * sc.w;

    float* op = out + (size_t)((b * HW + y) * HW + x0 + p0) * CH + c0;
#pragma unroll
    for (int px = 0; px < 8; ++px) {
        float4 r;
        r.x = sigmoidf_(acc[px].x * sc.x + sh.x);
        r.y = sigmoidf_(acc[px].y * sc.y + sh.y);
        r.z = sigmoidf_(acc[px].z * sc.z + sh.z);
        r.w = sigmoidf_(acc[px].w * sc.w + sh.w);
        *(float4*)(op + px * CH) = r;
    }
}

// ---------------- spatial attention (axis=-1 per pixel), warp per pixel ----
__global__ __launch_bounds__(256)
void spat_att_kernel()
{
    int p    = blockIdx.x * 8 + (threadIdx.x >> 5);
    int lane = threadIdx.x & 31;
    const float* qp = g_q + (size_t)p * CH;
    const float* kp = g_k + (size_t)p * CH;
    float tpl = 0.f, tpp = 0.f, tll = 0.f;
#pragma unroll
    for (int i = 0; i < 3; ++i) {
        float a = qp[lane + i * 32];
        float b = kp[lane + i * 32];
        tpl += a * b; tpp += a * a; tll += b * b;
    }
#pragma unroll
    for (int off = 16; off; off >>= 1) {
        tpl += __shfl_xor_sync(0xffffffffu, tpl, off);
        tpp += __shfl_xor_sync(0xffffffffu, tpp, off);
        tll += __shfl_xor_sync(0xffffffffu, tll, off);
    }
    if (lane == 0) g_att_spat[p] = ftanimoto(tpl, tpp, tll);
}

// ---------------- channel attention stage 1: partial sums per (b, 8-row chunk)
__global__ __launch_bounds__(192)
void chan_part_kernel()
{
    __shared__ float sp[2][96][3];
    const int t    = threadIdx.x;
    const int c    = t % 96;
    const int half = t / 96;
    const int blk  = blockIdx.x;         // 0..127
    const int b    = blk >> 4;
    const int yc   = blk & 15;
    const size_t base = (size_t)((b * HW + yc * 8) * HW) * CH + c;
    const float* qb = g_q + base;
    const float* kb = g_k + base;
    float tpl = 0.f, tpp = 0.f, tll = 0.f;
    const int start = half * 512;
#pragma unroll 4
    for (int i = 0; i < 512; ++i) {
        size_t off = (size_t)(start + i) * CH;
        float a = qb[off];
        float bb = kb[off];
        tpl += a * bb; tpp += a * a; tll += bb * bb;
    }
    sp[half][c][0] = tpl; sp[half][c][1] = tpp; sp[half][c][2] = tll;
    __syncthreads();
    if (t < 96) {
        float* o = g_part + blk * 288 + t * 3;
        o[0] = sp[0][t][0] + sp[1][t][0];
        o[1] = sp[0][t][1] + sp[1][t][1];
        o[2] = sp[0][t][2] + sp[1][t][2];
    }
}

// ---------------- channel attention stage 2: reduce partials, FT ----------
__global__ void chan_att_kernel()
{
    int b = blockIdx.x;
    int c = threadIdx.x;    // 96 threads
    float tpl = 0.f, tpp = 0.f, tll = 0.f;
#pragma unroll
    for (int i = 0; i < 16; ++i) {
        const float* pp = g_part + (b * 16 + i) * 288 + c * 3;
        tpl += pp[0]; tpp += pp[1]; tll += pp[2];
    }
    g_att_chan[b * CH + c] = ftanimoto(tpl, tpp, tll);
}

// ---------------- final combine + BN ----------------
__global__ __launch_bounds__(256)
void final_kernel(const float* __restrict__ gn, const float* __restrict__ bnb,
                  const float* __restrict__ mn, const float* __restrict__ vn,
                  float* __restrict__ out)
{
    int i4   = blockIdx.x * 256 + threadIdx.x;   // < 3145728
    int flat = i4 * 4;
    int pix  = flat / CH;
    int c    = flat % CH;
    int b    = pix >> 14;

    float4 v4 = *(const float4*)(g_v + (size_t)flat);
    float  as = g_att_spat[pix];
    float4 ac = *(const float4*)(g_att_chan + b * CH + c);
    float4 gg = *(const float4*)(gn  + c);
    float4 bb = *(const float4*)(bnb + c);
    float4 mm = *(const float4*)(mn  + c);
    float4 vv = *(const float4*)(vn  + c);

    float4 r;
    float s;
    s = gg.x * rsqrtf(vv.x + EPS_BN); r.x = (0.5f * v4.x * (ac.x + as) - mm.x) * s + bb.x;
    s = gg.y * rsqrtf(vv.y + EPS_BN); r.y = (0.5f * v4.y * (ac.y + as) - mm.y) * s + bb.y;
    s = gg.z * rsqrtf(vv.z + EPS_BN); r.z = (0.5f * v4.z * (ac.z + as) - mm.z) * s + bb.z;
    s = gg.w * rsqrtf(vv.w + EPS_BN); r.w = (0.5f * v4.w * (ac.w + as) - mm.w) * s + bb.w;
    *(float4*)(out + (size_t)flat) = r;
}

// ---------------- launch ----------------
extern "C" void kernel_launch(void* const* d_in, const int* in_sizes, int n_in,
                              void* d_out, int out_size)
{
    const float* x1 = (const float*)d_in[0];
    const float* x2 = (const float*)d_in[1];
    const float* x3 = (const float*)d_in[2];
    const float* wq = (const float*)d_in[3];
    const float* gq = (const float*)d_in[4];
    const float* bq = (const float*)d_in[5];
    const float* mq = (const float*)d_in[6];
    const float* vq = (const float*)d_in[7];
    const float* wk = (const float*)d_in[8];
    const float* gk = (const float*)d_in[9];
    const float* bk = (const float*)d_in[10];
    const float* mk = (const float*)d_in[11];
    const float* vk = (const float*)d_in[12];
    const float* wv = (const float*)d_in[13];
    const float* gv = (const float*)d_in[14];
    const float* bv = (const float*)d_in[15];
    const float* mv = (const float*)d_in[16];
    const float* vv = (const float*)d_in[17];
    const float* gn  = (const float*)d_in[18];
    const float* bnb = (const float*)d_in[19];
    const float* mn  = (const float*)d_in[20];
    const float* vn  = (const float*)d_in[21];

    float *qptr = nullptr, *kptr = nullptr, *vptr = nullptr;
    cudaGetSymbolAddress((void**)&qptr, g_q);
    cudaGetSymbolAddress((void**)&kptr, g_k);
    cudaGetSymbolAddress((void**)&vptr, g_v);

    dim3 cgrid(2, HW, NB);   // 2 x-tiles, 128 rows, 8 batches
    conv_bn_sig_kernel<<<cgrid, 192>>>(x1, wq, gq, bq, mq, vq, qptr);
    conv_bn_sig_kernel<<<cgrid, 192>>>(x2, wk, gk, bk, mk, vk, kptr);
    conv_bn_sig_kernel<<<cgrid, 192>>>(x3, wv, gv, bv, mv, vv, vptr);

    spat_att_kernel<<<NPIX / 8, 256>>>();
    chan_part_kernel<<<128, 192>>>();
    chan_att_kernel<<<NB, 96>>>();
    final_kernel<<<(NPIX * CH / 4) / 256, 256>>>(gn, bnb, mn, vn, (float*)d_out);
}

// round 5
// speedup vs baseline: 2.7990x; 2.7990x over previous
#include <cuda_runtime.h>
#include <cstdint>
#include <math.h>

#define EPS_BN    1e-5f
#define FT_SMOOTH 1e-5f

#define CH   96
#define HW   128
#define NB   8
#define NPIX (NB*HW*HW)        /* 131072 */

// ======================= device scratch =======================
__device__ float g_q[(size_t)NPIX * CH];
__device__ float g_k[(size_t)NPIX * CH];
__device__ float g_v[(size_t)NPIX * CH];
__device__ float g_att_spat[NPIX];
__device__ float g_part[128 * 96 * 3];
__device__ float g_att_chan[NB * CH];
// Pre-converted tf32 weights: [3 convs][27 chunks][32 k][96 cout]
__device__ float g_Bw[3 * 27 * 32 * 96];

// ======================= math helpers =======================
__device__ __forceinline__ float ftanimoto(float tpl, float tpp, float tll) {
    float num = tpl + FT_SMOOTH;
    float s   = tpp + tll;
    float den = 0.f;
#pragma unroll
    for (int d = 0; d < 5; ++d) {
        float a = (float)(1 << d);
        float b = -(2.f * a - 1.f);
        den += 1.f / (a * s + b * tpl + FT_SMOOTH);
    }
    return num * den * 0.2f;
}
__device__ __forceinline__ float sigmoidf_(float x) { return 1.f / (1.f + expf(-x)); }
__device__ __forceinline__ float f2tf32f(float v) {
    uint32_t t; asm("cvt.rna.tf32.f32 %0, %1;" : "=r"(t) : "f"(v));
    return __uint_as_float(t);
}

// mma.sync m16n8k8 tf32 (HMMA path; sm_80+ PTX, valid on compute_103)
__device__ __forceinline__ void mma_tf32(float4& d, const uint32_t a[4], const uint32_t b[2]) {
    asm volatile(
        "mma.sync.aligned.m16n8k8.row.col.f32.tf32.tf32.f32 "
        "{%0,%1,%2,%3}, {%4,%5,%6,%7}, {%8,%9}, {%0,%1,%2,%3};"
        : "+f"(d.x), "+f"(d.y), "+f"(d.z), "+f"(d.w)
        : "r"(a[0]), "r"(a[1]), "r"(a[2]), "r"(a[3]), "r"(b[0]), "r"(b[1]));
}

// ======================= weight prep =======================
// block = (conv*27 + chunk), 96 threads (one per cout)
// g_Bw layout per chunk: [k=0..31][cout=0..95], tf32-rounded
__global__ void prep_weights(const float* __restrict__ wq,
                             const float* __restrict__ wk,
                             const float* __restrict__ wv)
{
    int conv = blockIdx.x / 27;
    int c    = blockIdx.x % 27;
    const float* w = (conv == 0) ? wq : (conv == 1) ? wk : wv;
    int dy = c / 9, dx = (c % 9) / 3, ci0 = (c % 3) * 32;
    int co = threadIdx.x;                       // 0..95
    float* dst = g_Bw + (size_t)(conv * 27 + c) * (32 * 96);
#pragma unroll 4
    for (int k = 0; k < 32; ++k) {
        float v = w[(((dy * 3 + dx) * CH) + ci0 + k) * CH + co];
        dst[k * 96 + co] = f2tf32f(v);
    }
}

// ======================= conv via mma.sync TF32 =======================
// Block: 128 threads (4 warps). Tile: 64 pixels (row segment) x 96 couts.
// Warp: 16 px x 96 couts = 12 m16n8k8 fragments, C = 48 regs.
// K loop: 27 chunks of 32 (dy, dx, ci-third), double-buffered smem,
// register prefetch of chunk c+1 during chunk c's MMAs.
#define A_STRIDE 36    /* frag LDS bank = 4*gid+tig : conflict-free */
#define B_STRIDE 104   /* frag LDS bank = 8*tig+gid : conflict-free */

__global__ void __launch_bounds__(128)
conv_mma_kernel(const float* __restrict__ x1, const float* __restrict__ x2,
                const float* __restrict__ x3,
                const float* __restrict__ gq, const float* __restrict__ bq,
                const float* __restrict__ mq, const float* __restrict__ vq,
                const float* __restrict__ gk, const float* __restrict__ bk,
                const float* __restrict__ mk, const float* __restrict__ vk,
                const float* __restrict__ gv, const float* __restrict__ bv,
                const float* __restrict__ mv, const float* __restrict__ vvv)
{
    __shared__ __align__(16) float sA[2][64 * A_STRIDE];   // 2 x 9216 B
    __shared__ __align__(16) float sB[2][32 * B_STRIDE];   // 2 x 13312 B
    __shared__ float s_scale[CH], s_shift[CH];

    const int tid  = threadIdx.x;
    const int conv = blockIdx.y;
    const int t    = blockIdx.x;            // 0..2047
    const int b    = t >> 8;                // batch
    const int y    = (t >> 1) & 127;        // output row
    const int x0   = (t & 1) * 64;          // x tile base

    const float* xin = (conv == 0) ? x1 : (conv == 1) ? x2 : x3;
    float* outp      = (conv == 0) ? g_q : (conv == 1) ? g_k : g_v;

    if (tid < CH) {
        const float* gm = (conv == 0) ? gq : (conv == 1) ? gk : gv;
        const float* bt = (conv == 0) ? bq : (conv == 1) ? bk : bv;
        const float* mu = (conv == 0) ? mq : (conv == 1) ? mk : mv;
        const float* vr = (conv == 0) ? vq : (conv == 1) ? vk : vvv;
        float s = gm[tid] * rsqrtf(vr[tid] + EPS_BN);
        s_scale[tid] = s;
        s_shift[tid] = bt[tid] - mu[tid] * s;
    }

    const int lane = tid & 31;
    const int wp   = tid >> 5;
    const int gid  = lane >> 2;   // 0..7
    const int tig  = lane & 3;    // 0..3

    // staging roles
    const int s_px = tid >> 1;          // 0..63 pixel within tile
    const int s_h  = (tid & 1) * 16;    // ci offset 0/16

    const size_t imgbase = (size_t)b * (HW * HW * CH);
    const float* Bw = g_Bw + (size_t)conv * 27 * (32 * 96);

    float4 a_pre[4];    // 16 floats: input slice
    uint4  b_pre[6];    // 24 floats: weight slice

    auto load_chunk = [&](int c) {
        const int dy  = c / 9;
        const int dx  = (c % 9) / 3;
        const int ci0 = (c % 3) * 32;
        const int gy  = y + dy - 1;
        const int gx  = x0 + s_px + dx - 1;
        if ((unsigned)gy < (unsigned)HW && (unsigned)gx < (unsigned)HW) {
            const float4* src = (const float4*)(xin + imgbase +
                                 ((size_t)(gy * HW + gx) * CH + ci0 + s_h));
#pragma unroll
            for (int j = 0; j < 4; ++j) a_pre[j] = src[j];
        } else {
#pragma unroll
            for (int j = 0; j < 4; ++j) a_pre[j] = make_float4(0.f, 0.f, 0.f, 0.f);
        }
        const uint4* wsrc = (const uint4*)(Bw + (size_t)c * (32 * 96));
#pragma unroll
        for (int i = 0; i < 6; ++i) b_pre[i] = wsrc[tid + i * 128];
    };

    auto store_chunk = [&](int buf) {
        float4* adst = (float4*)(sA[buf] + s_px * A_STRIDE + s_h);
#pragma unroll
        for (int j = 0; j < 4; ++j) {
            float4 v = a_pre[j];
            adst[j] = make_float4(f2tf32f(v.x), f2tf32f(v.y), f2tf32f(v.z), f2tf32f(v.w));
        }
#pragma unroll
        for (int i = 0; i < 6; ++i) {
            int idx = tid + i * 128;        // float4 index over [32][24]
            int k   = idx / 24;
            int c4  = idx % 24;
            *(uint4*)(sB[buf] + k * B_STRIDE + c4 * 4) = b_pre[i];
        }
    };

    float4 C[12];
#pragma unroll
    for (int i = 0; i < 12; ++i) C[i] = make_float4(0.f, 0.f, 0.f, 0.f);

    load_chunk(0);
    store_chunk(0);
    __syncthreads();

    for (int c = 0; c < 27; ++c) {
        const int cur = c & 1;
        if (c < 26) load_chunk(c + 1);

        const float* A  = sA[cur] + (wp * 16 + gid) * A_STRIDE + tig;
        const float* B0 = sB[cur] + tig * B_STRIDE + gid;
#pragma unroll
        for (int ks = 0; ks < 4; ++ks) {
            uint32_t a[4];
            a[0] = __float_as_uint(A[ks * 8]);
            a[1] = __float_as_uint(A[8 * A_STRIDE + ks * 8]);
            a[2] = __float_as_uint(A[ks * 8 + 4]);
            a[3] = __float_as_uint(A[8 * A_STRIDE + ks * 8 + 4]);
            const float* Brow = B0 + ks * 8 * B_STRIDE;
#pragma unroll
            for (int nb = 0; nb < 12; ++nb) {
                uint32_t bb[2];
                bb[0] = __float_as_uint(Brow[nb * 8]);
                bb[1] = __float_as_uint(Brow[4 * B_STRIDE + nb * 8]);
                mma_tf32(C[nb], a, bb);
            }
        }
        if (c < 26) {
            store_chunk((c + 1) & 1);
            __syncthreads();
        }
    }

    // ---- epilogue: BN + sigmoid, float2 stores (c0,c1 adjacent cols) ----
    const int px = x0 + wp * 16 + gid;
    float* orow0 = outp + imgbase + ((size_t)(y * HW) + px) * CH;
    float* orow1 = orow0 + 8 * CH;      // pixel px+8
#pragma unroll
    for (int nb = 0; nb < 12; ++nb) {
        int col = nb * 8 + 2 * tig;
        float sc0 = s_scale[col],     sh0 = s_shift[col];
        float sc1 = s_scale[col + 1], sh1 = s_shift[col + 1];
        float2 r0, r1;
        r0.x = sigmoidf_(C[nb].x * sc0 + sh0);
        r0.y = sigmoidf_(C[nb].y * sc1 + sh1);
        r1.x = sigmoidf_(C[nb].z * sc0 + sh0);
        r1.y = sigmoidf_(C[nb].w * sc1 + sh1);
        *(float2*)(orow0 + col) = r0;
        *(float2*)(orow1 + col) = r1;
    }
}

// ======================= attention + final (passing, from R1) =======================
__global__ __launch_bounds__(256)
void spat_att_kernel()
{
    int p    = blockIdx.x * 8 + (threadIdx.x >> 5);
    int lane = threadIdx.x & 31;
    const float* qp = g_q + (size_t)p * CH;
    const float* kp = g_k + (size_t)p * CH;
    float tpl = 0.f, tpp = 0.f, tll = 0.f;
#pragma unroll
    for (int i = 0; i < 3; ++i) {
        float a = qp[lane + i * 32];
        float b = kp[lane + i * 32];
        tpl += a * b; tpp += a * a; tll += b * b;
    }
#pragma unroll
    for (int off = 16; off; off >>= 1) {
        tpl += __shfl_xor_sync(0xffffffffu, tpl, off);
        tpp += __shfl_xor_sync(0xffffffffu, tpp, off);
        tll += __shfl_xor_sync(0xffffffffu, tll, off);
    }
    if (lane == 0) g_att_spat[p] = ftanimoto(tpl, tpp, tll);
}

__global__ __launch_bounds__(192)
void chan_part_kernel()
{
    __shared__ float sp[2][96][3];
    const int t    = threadIdx.x;
    const int c    = t % 96;
    const int half = t / 96;
    const int blk  = blockIdx.x;         // 0..127
    const int b    = blk >> 4;
    const int yc   = blk & 15;
    const size_t base = (size_t)((b * HW + yc * 8) * HW) * CH + c;
    const float* qb = g_q + base;
    const float* kb = g_k + base;
    float tpl = 0.f, tpp = 0.f, tll = 0.f;
    const int start = half * 512;
#pragma unroll 4
    for (int i = 0; i < 512; ++i) {
        size_t off = (size_t)(start + i) * CH;
        float a = qb[off];
        float bb = kb[off];
        tpl += a * bb; tpp += a * a; tll += bb * bb;
    }
    sp[half][c][0] = tpl; sp[half][c][1] = tpp; sp[half][c][2] = tll;
    __syncthreads();
    if (t < 96) {
        float* o = g_part + blk * 288 + t * 3;
        o[0] = sp[0][t][0] + sp[1][t][0];
        o[1] = sp[0][t][1] + sp[1][t][1];
        o[2] = sp[0][t][2] + sp[1][t][2];
    }
}

__global__ void chan_att_kernel()
{
    int b = blockIdx.x;
    int c = threadIdx.x;    // 96 threads
    float tpl = 0.f, tpp = 0.f, tll = 0.f;
#pragma unroll
    for (int i = 0; i < 16; ++i) {
        const float* pp = g_part + (b * 16 + i) * 288 + c * 3;
        tpl += pp[0]; tpp += pp[1]; tll += pp[2];
    }
    g_att_chan[b * CH + c] = ftanimoto(tpl, tpp, tll);
}

__global__ __launch_bounds__(256)
void final_kernel(const float* __restrict__ gn, const float* __restrict__ bnb,
                  const float* __restrict__ mn, const float* __restrict__ vn,
                  float* __restrict__ out)
{
    int i4   = blockIdx.x * 256 + threadIdx.x;
    int flat = i4 * 4;
    int pix  = flat / CH;
    int c    = flat % CH;
    int b    = pix >> 14;

    float4 v4 = *(const float4*)(g_v + (size_t)flat);
    float  as = g_att_spat[pix];
    float4 ac = *(const float4*)(g_att_chan + b * CH + c);
    float4 gg = *(const float4*)(gn  + c);
    float4 bb = *(const float4*)(bnb + c);
    float4 mm = *(const float4*)(mn  + c);
    float4 vv = *(const float4*)(vn  + c);

    float4 r;
    float s;
    s = gg.x * rsqrtf(vv.x + EPS_BN); r.x = (0.5f * v4.x * (ac.x + as) - mm.x) * s + bb.x;
    s = gg.y * rsqrtf(vv.y + EPS_BN); r.y = (0.5f * v4.y * (ac.y + as) - mm.y) * s + bb.y;
    s = gg.z * rsqrtf(vv.z + EPS_BN); r.z = (0.5f * v4.z * (ac.z + as) - mm.z) * s + bb.z;
    s = gg.w * rsqrtf(vv.w + EPS_BN); r.w = (0.5f * v4.w * (ac.w + as) - mm.w) * s + bb.w;
    *(float4*)(out + (size_t)flat) = r;
}

// ======================= launch =======================
extern "C" void kernel_launch(void* const* d_in, const int* in_sizes, int n_in,
                              void* d_out, int out_size)
{
    const float* x1 = (const float*)d_in[0];
    const float* x2 = (const float*)d_in[1];
    const float* x3 = (const float*)d_in[2];
    const float* wq = (const float*)d_in[3];
    const float* gq = (const float*)d_in[4];
    const float* bq = (const float*)d_in[5];
    const float* mq = (const float*)d_in[6];
    const float* vq = (const float*)d_in[7];
    const float* wk = (const float*)d_in[8];
    const float* gk = (const float*)d_in[9];
    const float* bk = (const float*)d_in[10];
    const float* mk = (const float*)d_in[11];
    const float* vk = (const float*)d_in[12];
    const float* wv = (const float*)d_in[13];
    const float* gv = (const float*)d_in[14];
    const float* bv = (const float*)d_in[15];
    const float* mv = (const float*)d_in[16];
    const float* vv = (const float*)d_in[17];
    const float* gn  = (const float*)d_in[18];
    const float* bnb = (const float*)d_in[19];
    const float* mn  = (const float*)d_in[20];
    const float* vn  = (const float*)d_in[21];

    prep_weights<<<81, 96>>>(wq, wk, wv);

    dim3 cgrid(2048, 3);   // (2 x-tiles * 128 rows * 8 batches) x 3 convs
    conv_mma_kernel<<<cgrid, 128>>>(x1, x2, x3,
                                    gq, bq, mq, vq,
                                    gk, bk, mk, vk,
                                    gv, bv, mv, vv);

    spat_att_kernel<<<NPIX / 8, 256>>>();
    chan_part_kernel<<<128, 192>>>();
    chan_att_kernel<<<NB, 96>>>();
    final_kernel<<<(NPIX * CH / 4) / 256, 256>>>(gn, bnb, mn, vn, (float*)d_out);
}